// round 3
// baseline (speedup 1.0000x reference)
#include <cuda_runtime.h>
#include <cuda_bf16.h>

#define BB 256
#define TT 256
#define CP1 129
#define HH 128
#define G1 384
#define PRED_N (BB * (TT - 1) * 128)
#define PAR_N  (BB * TT * 2)

// ---------------- scratch: __device__ globals (no runtime allocation) -------
__device__ float g_gi1[(size_t)BB * TT * G1];   // (b,t,384) layer-1 input proj
__device__ float g_out1[(size_t)BB * TT * HH];  // (b,t,128) layer-1 outputs
__device__ float g_gi2[(size_t)BB * TT * 6];    // (b,t,6)   layer-2 input proj

// ---------------- math helpers ----------------------------------------------
__device__ __forceinline__ float sigf(float v) {
    return __fdividef(1.f, 1.f + __expf(-v));
}
__device__ __forceinline__ float tanh_(float v) {
    return __fdividef(2.f, 1.f + __expf(-2.f * v)) - 1.f;
}

// ---------------- K1: gi1 = x @ Wih1^T + bih1 -------------------------------
// grid (4 t-tiles, B, 6 n-tiles), block 256. 64x64 tile, K=129 in chunks.
__global__ void k_gi1(const float* __restrict__ x, const int* __restrict__ lengths,
                      const float* __restrict__ Wih1, const float* __restrict__ bih1) {
    int t0 = blockIdx.x * 64, b = blockIdx.y, n0 = blockIdx.z * 64;
    if (t0 >= __ldg(lengths + b)) return;  // fully-masked tile: gi1 never read

    __shared__ __align__(16) float sA[64 * 68];
    __shared__ __align__(16) float sW[64 * 68];
    float acc[4][4] = {};
    const float* xb = x + ((size_t)(b * TT + t0)) * CP1;
    int tx = threadIdx.x & 15, ty = threadIdx.x >> 4;

    for (int kc = 0; kc < CP1; kc += 64) {
        int kl = min(64, CP1 - kc);
        __syncthreads();
        for (int idx = threadIdx.x; idx < 64 * kl; idx += 256) {
            int m = idx / kl, k = idx - m * kl;
            sA[m * 68 + k] = xb[m * CP1 + kc + k];
        }
        for (int idx = threadIdx.x; idx < 64 * kl; idx += 256) {
            int n = idx / kl, k = idx - n * kl;
            sW[k * 68 + n] = Wih1[(size_t)(n0 + n) * CP1 + kc + k];
        }
        __syncthreads();
        for (int k = 0; k < kl; k++) {
            float4 w = *(const float4*)&sW[k * 68 + tx * 4];
#pragma unroll
            for (int i = 0; i < 4; i++) {
                float a = sA[(ty * 4 + i) * 68 + k];
                acc[i][0] += a * w.x; acc[i][1] += a * w.y;
                acc[i][2] += a * w.z; acc[i][3] += a * w.w;
            }
        }
    }
    float4 bb = *(const float4*)(bih1 + n0 + tx * 4);
#pragma unroll
    for (int i = 0; i < 4; i++) {
        float4 o = make_float4(acc[i][0] + bb.x, acc[i][1] + bb.y,
                               acc[i][2] + bb.z, acc[i][3] + bb.w);
        *(float4*)&g_gi1[((size_t)(b * TT + t0 + ty * 4 + i)) * G1 + n0 + tx * 4] = o;
    }
}

// ---------------- K2: layer-1 GRU recurrence --------------------------------
// 128 CTAs; CTA p runs batch rows p and 255-p (lengths sorted desc => balanced).
// Thread g keeps Whh1 row g in registers (32 float4).
__global__ void __launch_bounds__(384, 1)
k_recur1(const int* __restrict__ lengths, const float* __restrict__ h0_1,
         const float* __restrict__ Whh1, const float* __restrict__ bhh1) {
    int g = threadIdx.x;
    float4 W4[32];
    const float4* wr = (const float4*)(Whh1 + (size_t)g * HH);
#pragma unroll
    for (int i = 0; i < 32; i++) W4[i] = wr[i];
    float bh = bhh1[g];

    __shared__ __align__(16) float s_h[HH];
    __shared__ float s_gh[G1];

#pragma unroll 1
    for (int rsel = 0; rsel < 2; rsel++) {
        int b = rsel ? (255 - (int)blockIdx.x) : (int)blockIdx.x;
        int len = __ldg(lengths + b);
        if (g < HH) s_h[g] = h0_1[b * HH + g];
        __syncthreads();

        const float* gi = g_gi1 + (size_t)b * TT * G1;
        float* o1 = g_out1 + (size_t)b * TT * HH;
        float pr = 0.f, pz = 0.f, pn = 0.f;
        if (g < HH) { pr = gi[g]; pz = gi[HH + g]; pn = gi[2 * HH + g]; }

#pragma unroll 1
        for (int t = 0; t < len; t++) {
            float a0 = 0.f, a1 = 0.f, a2 = 0.f, a3 = 0.f;
            const float4* h4 = (const float4*)s_h;
#pragma unroll
            for (int i = 0; i < 32; i += 4) {
                float4 ha = h4[i];
                a0 += W4[i].x * ha.x + W4[i].y * ha.y + W4[i].z * ha.z + W4[i].w * ha.w;
                float4 hb = h4[i + 1];
                a1 += W4[i+1].x * hb.x + W4[i+1].y * hb.y + W4[i+1].z * hb.z + W4[i+1].w * hb.w;
                float4 hc = h4[i + 2];
                a2 += W4[i+2].x * hc.x + W4[i+2].y * hc.y + W4[i+2].z * hc.z + W4[i+2].w * hc.w;
                float4 hd = h4[i + 3];
                a3 += W4[i+3].x * hd.x + W4[i+3].y * hd.y + W4[i+3].z * hd.z + W4[i+3].w * hd.w;
            }
            s_gh[g] = a0 + a1 + a2 + a3 + bh;
            __syncthreads();

            if (g < HH) {
                float r = sigf(pr + s_gh[g]);
                float z = sigf(pz + s_gh[HH + g]);
                float n = tanh_(pn + r * s_gh[2 * HH + g]);
                float hn = (1.f - z) * n + z * s_h[g];
                o1[(size_t)t * HH + g] = hn;
                if (t + 1 < len) {  // prefetch next step's input projections
                    const float* gn = gi + (size_t)(t + 1) * G1;
                    pr = gn[g]; pz = gn[HH + g]; pn = gn[2 * HH + g];
                }
                s_h[g] = hn;
            }
            __syncthreads();
        }
    }
}

// ---------------- K3: gi2 = out1 @ Wih2^T + bih2 ----------------------------
// grid (4 t-tiles, B), block 384 = 64 timesteps x 6 gates.
__global__ void k_gi2(const int* __restrict__ lengths, const float* __restrict__ Wih2,
                      const float* __restrict__ bih2) {
    int t0 = blockIdx.x * 64, b = blockIdx.y;
    int len = __ldg(lengths + b);
    if (t0 >= len) return;

    __shared__ float sh[64 * HH];
    __shared__ float sw[6 * HH];
    const float* o1 = g_out1 + ((size_t)(b * TT + t0)) * HH;
    for (int i = threadIdx.x; i < 64 * HH; i += 384) sh[i] = o1[i];
    for (int i = threadIdx.x; i < 6 * HH; i += 384) sw[i] = Wih2[i];
    __syncthreads();

    int tt = threadIdx.x / 6, gg = threadIdx.x - tt * 6;
    if (tt < 64 && (t0 + tt) < len) {
        float acc = bih2[gg];
        const float* hr = sh + tt * HH;
        const float* w = sw + gg * HH;
#pragma unroll 8
        for (int k = 0; k < HH; k++) acc += hr[k] * w[k];
        g_gi2[((size_t)(b * TT + t0 + tt)) * 6 + gg] = acc;
    }
}

// ---------------- K4: FC head preds = [out1, x_time] @ Wfc^T + bfc ----------
// grid (4 t-tiles, B, 2 n-tiles), block 256. Zero-fills masked positions.
__global__ void k_fc(const float* __restrict__ x, const int* __restrict__ lengths,
                     const float* __restrict__ Wfc, const float* __restrict__ bfc,
                     float* __restrict__ out) {
    int t0 = blockIdx.x * 64, b = blockIdx.y, n0 = blockIdx.z * 64;
    int len = __ldg(lengths + b);
    int rows = min(64, (TT - 1) - t0);
    float* ob = out + ((size_t)b * (TT - 1)) * 128;

    if (t0 >= len - 1) {  // fully masked tile: zero-fill, skip GEMM
        for (int idx = threadIdx.x; idx < rows * 64; idx += 256) {
            int m = idx >> 6, n = idx & 63;
            ob[(size_t)(t0 + m) * 128 + n0 + n] = 0.f;
        }
        return;
    }

    __shared__ __align__(16) float sA[64 * 68];
    __shared__ __align__(16) float sW[64 * 68];
    float acc[4][4] = {};
    int tx = threadIdx.x & 15, ty = threadIdx.x >> 4;

    for (int kc = 0; kc < CP1; kc += 64) {
        int kl = min(64, CP1 - kc);
        __syncthreads();
        for (int idx = threadIdx.x; idx < 64 * kl; idx += 256) {
            int m = idx / kl, k = idx - m * kl;
            int kg = kc + k, t = t0 + m;  // t <= 254, always in-bounds
            float v;
            if (kg < HH) v = g_out1[((size_t)(b * TT + t)) * HH + kg];
            else         v = x[((size_t)(b * TT + t)) * CP1];  // time feature x[...,0]
            sA[m * 68 + k] = v;
        }
        for (int idx = threadIdx.x; idx < 64 * kl; idx += 256) {
            int n = idx / kl, k = idx - n * kl;
            sW[k * 68 + n] = Wfc[(size_t)(n0 + n) * CP1 + kc + k];
        }
        __syncthreads();
        for (int k = 0; k < kl; k++) {
            float4 w = *(const float4*)&sW[k * 68 + tx * 4];
#pragma unroll
            for (int i = 0; i < 4; i++) {
                float a = sA[(ty * 4 + i) * 68 + k];
                acc[i][0] += a * w.x; acc[i][1] += a * w.y;
                acc[i][2] += a * w.z; acc[i][3] += a * w.w;
            }
        }
    }
    float4 bbv = *(const float4*)(bfc + n0 + tx * 4);
#pragma unroll
    for (int i = 0; i < 4; i++) {
        int t = t0 + ty * 4 + i;
        if (t >= TT - 1) continue;
        float4 o;
        if (t < len - 1)
            o = make_float4(acc[i][0] + bbv.x, acc[i][1] + bbv.y,
                            acc[i][2] + bbv.z, acc[i][3] + bbv.w);
        else
            o = make_float4(0.f, 0.f, 0.f, 0.f);
        *(float4*)&ob[(size_t)t * 128 + n0 + tx * 4] = o;
    }
}

// ---------------- K5: layer-2 recurrence (P=2) + params + lengths tail ------
__global__ void k_recur2(const int* __restrict__ lengths, const float* __restrict__ h0_2,
                         const float* __restrict__ Whh2, const float* __restrict__ bhh2,
                         float* __restrict__ out) {
    int b = blockIdx.x * 32 + threadIdx.x;
    if (b >= BB) return;
    int len = __ldg(lengths + b);
    float u0 = h0_2[b * 2], u1 = h0_2[b * 2 + 1];
    float w[12], bb[6];
#pragma unroll
    for (int i = 0; i < 12; i++) w[i] = Whh2[i];
#pragma unroll
    for (int i = 0; i < 6; i++) bb[i] = bhh2[i];

    float* par = out + PRED_N + (size_t)b * TT * 2;
    const float* gi = g_gi2 + (size_t)b * TT * 6;

    for (int t = 0; t < len; t++) {
        const float* g6 = gi + (size_t)t * 6;
        float hr0 = w[0]  * u0 + w[1]  * u1 + bb[0];
        float hr1 = w[2]  * u0 + w[3]  * u1 + bb[1];
        float hz0 = w[4]  * u0 + w[5]  * u1 + bb[2];
        float hz1 = w[6]  * u0 + w[7]  * u1 + bb[3];
        float hn0 = w[8]  * u0 + w[9]  * u1 + bb[4];
        float hn1 = w[10] * u0 + w[11] * u1 + bb[5];
        float r0 = sigf(g6[0] + hr0), r1 = sigf(g6[1] + hr1);
        float z0 = sigf(g6[2] + hz0), z1 = sigf(g6[3] + hz1);
        float n0 = tanh_(g6[4] + r0 * hn0), n1 = tanh_(g6[5] + r1 * hn1);
        u0 = (1.f - z0) * n0 + z0 * u0;
        u1 = (1.f - z1) * n1 + z1 * u1;
        par[t * 2]     = __expf(-u0);
        par[t * 2 + 1] = __expf(-u1);
    }
    for (int t = len; t < TT; t++) { par[t * 2] = 1.f; par[t * 2 + 1] = 1.f; }
    out[PRED_N + PAR_N + b] = (float)len;  // lengths tail as f32
}

// ---------------- launch -----------------------------------------------------
extern "C" void kernel_launch(void* const* d_in, const int* in_sizes, int n_in,
                              void* d_out, int out_size) {
    const float* x      = (const float*)d_in[0];
    const int*   lens   = (const int*)  d_in[1];
    const float* h0_1   = (const float*)d_in[2];
    const float* h0_2   = (const float*)d_in[3];
    const float* Wih1   = (const float*)d_in[4];
    const float* Whh1   = (const float*)d_in[5];
    const float* bih1   = (const float*)d_in[6];
    const float* bhh1   = (const float*)d_in[7];
    const float* Wih2   = (const float*)d_in[8];
    const float* Whh2   = (const float*)d_in[9];
    const float* bih2   = (const float*)d_in[10];
    const float* bhh2   = (const float*)d_in[11];
    const float* Wfc    = (const float*)d_in[12];
    const float* bfc    = (const float*)d_in[13];
    float* out = (float*)d_out;

    k_gi1  <<<dim3(4, BB, 6), 256>>>(x, lens, Wih1, bih1);
    k_recur1<<<128, 384>>>(lens, h0_1, Whh1, bhh1);
    k_gi2  <<<dim3(4, BB), 384>>>(lens, Wih2, bih2);
    k_fc   <<<dim3(4, BB, 2), 256>>>(x, lens, Wfc, bfc, out);
    k_recur2<<<8, 32>>>(lens, h0_2, Whh2, bhh2, out);
}